// round 7
// baseline (speedup 1.0000x reference)
#include <cuda_runtime.h>
#include <cstddef>
#include <cstdint>

#define BATCH   64
#define NCAPS   32
#define NROUTES 2048
#define INDIM   16
#define OUTDIM  32
#define NITERS  3
#define THREADS 512
#define CSZ     8            // cluster size = route chunks
#define BPC     8            // batches per CTA
#define RPC     (NROUTES / CSZ)    // 256 routes per CTA
#define RSTAGE  (RPC / 2)          // 128 routes per stage

// ---- SMEM layout (floats) ----
// sp rows: row(b, r) = b*128 + r (r = stage-local route), stride 33 -> conflict-free
#define SPS       33
#define OFF_SP    0                        // 1024 * 33 = 33792
#define OFF_VSH   (1024 * SPS)             // 8 * 32
#define OFF_WREDM (OFF_VSH + 256)          // 16
#define OFF_WREDZ (OFF_WREDM + 16)         // 16
#define OFF_WVEC  (OFF_WREDZ + 16)         // 16 * 32
#define OFF_EXCH  (OFF_WVEC + 512)         // 8 * 34  (m, Z, s~[32]) per batch
#define SMEM_FLOATS (OFF_EXCH + 8 * 34)
#define SMEM_BYTES  (SMEM_FLOATS * 4)

__device__ __forceinline__ uint32_t smem_u32(const void* p) {
    uint32_t a;
    asm("{ .reg .u64 t; cvta.to.shared.u64 t, %1; cvt.u32.u64 %0, t; }" : "=r"(a) : "l"(p));
    return a;
}
__device__ __forceinline__ float dsmem_ld(const float* p, uint32_t rk) {
    uint32_t ra; float v;
    asm volatile("mapa.shared::cluster.u32 %0, %1, %2;" : "=r"(ra) : "r"(smem_u32(p)), "r"(rk));
    asm volatile("ld.shared::cluster.f32 %0, [%1];" : "=f"(v) : "r"(ra));
    return v;
}
#define CLUSTER_SYNC() do { \
    asm volatile("barrier.cluster.arrive.aligned;" ::: "memory"); \
    asm volatile("barrier.cluster.wait.aligned;" ::: "memory"); } while (0)

__global__ void __launch_bounds__(THREADS, 1)
caps_cluster_kernel(const float* __restrict__ x,
                    const float* __restrict__ W,
                    float* __restrict__ out)
{
    extern __shared__ float sm[];
    float* sp    = sm + OFF_SP;
    float* Vsh   = sm + OFF_VSH;
    float* wredM = sm + OFF_WREDM;
    float* wredZ = sm + OFF_WREDZ;
    float* wvec  = sm + OFF_WVEC;
    float* exch  = sm + OFF_EXCH;

    const int t    = threadIdx.x;
    const int lane = t & 31;
    const int wid  = t >> 5;
    const int rsub = lane >> 3;        // 0..3 route within quad
    const int c4   = lane & 7;         // 0..7 float4 col group
    const int cid  = blockIdx.x >> 3;  // cluster id
    const uint32_t rank = blockIdx.x & 7;   // == %cluster_ctarank (x-contiguous clusters)
    const int c    = cid >> 3;
    const int bg   = cid & 7;
    const int b0g  = bg * BPC;         // global batch base
    const int r0g  = (int)rank * RPC;  // global route base

    if (t < BPC * 32) Vsh[t] = 0.f;

    float rf[64];   // stage-A register rows: 2 rows x 32

    // ================= Phase 1: priors, two stages =================
    for (int stage = 0; stage < 2; stage++) {
        const int rlbase = wid * 8;    // 8 routes per warp per stage
#pragma unroll
        for (int j = 0; j < 8; j += 4) {
            const int rl = rlbase + j;                   // stage-local quad base
            const int rg = r0g + stage * RSTAGE + rl + rsub;
            const float4* wr = reinterpret_cast<const float4*>(
                W + ((size_t)c * NROUTES + rg) * (INDIM * OUTDIM)) + c4;
#pragma unroll
            for (int p = 0; p < 2; p++) {                // batch-group passes
                const int bb = p * 4;
                float a0[4], a1[4], a2[4], a3[4];
#pragma unroll
                for (int q = 0; q < 4; q++) { a0[q] = a1[q] = a2[q] = a3[q] = 0.f; }
#pragma unroll
                for (int g = 0; g < 4; g++) {
                    float4 w0 = __ldg(wr + (g * 4 + 0) * 8);
                    float4 w1 = __ldg(wr + (g * 4 + 1) * 8);
                    float4 w2 = __ldg(wr + (g * 4 + 2) * 8);
                    float4 w3 = __ldg(wr + (g * 4 + 3) * 8);
                    float4 x0 = __ldg(reinterpret_cast<const float4*>(
                        x + ((size_t)(b0g + bb + 0) * NROUTES + rg) * INDIM) + g);
                    float4 x1 = __ldg(reinterpret_cast<const float4*>(
                        x + ((size_t)(b0g + bb + 1) * NROUTES + rg) * INDIM) + g);
                    float4 x2 = __ldg(reinterpret_cast<const float4*>(
                        x + ((size_t)(b0g + bb + 2) * NROUTES + rg) * INDIM) + g);
                    float4 x3 = __ldg(reinterpret_cast<const float4*>(
                        x + ((size_t)(b0g + bb + 3) * NROUTES + rg) * INDIM) + g);

                    a0[0] = fmaf(x0.x, w0.x, a0[0]); a0[1] = fmaf(x0.x, w0.y, a0[1]);
                    a0[2] = fmaf(x0.x, w0.z, a0[2]); a0[3] = fmaf(x0.x, w0.w, a0[3]);
                    a0[0] = fmaf(x0.y, w1.x, a0[0]); a0[1] = fmaf(x0.y, w1.y, a0[1]);
                    a0[2] = fmaf(x0.y, w1.z, a0[2]); a0[3] = fmaf(x0.y, w1.w, a0[3]);
                    a0[0] = fmaf(x0.z, w2.x, a0[0]); a0[1] = fmaf(x0.z, w2.y, a0[1]);
                    a0[2] = fmaf(x0.z, w2.z, a0[2]); a0[3] = fmaf(x0.z, w2.w, a0[3]);
                    a0[0] = fmaf(x0.w, w3.x, a0[0]); a0[1] = fmaf(x0.w, w3.y, a0[1]);
                    a0[2] = fmaf(x0.w, w3.z, a0[2]); a0[3] = fmaf(x0.w, w3.w, a0[3]);

                    a1[0] = fmaf(x1.x, w0.x, a1[0]); a1[1] = fmaf(x1.x, w0.y, a1[1]);
                    a1[2] = fmaf(x1.x, w0.z, a1[2]); a1[3] = fmaf(x1.x, w0.w, a1[3]);
                    a1[0] = fmaf(x1.y, w1.x, a1[0]); a1[1] = fmaf(x1.y, w1.y, a1[1]);
                    a1[2] = fmaf(x1.y, w1.z, a1[2]); a1[3] = fmaf(x1.y, w1.w, a1[3]);
                    a1[0] = fmaf(x1.z, w2.x, a1[0]); a1[1] = fmaf(x1.z, w2.y, a1[1]);
                    a1[2] = fmaf(x1.z, w2.z, a1[2]); a1[3] = fmaf(x1.z, w2.w, a1[3]);
                    a1[0] = fmaf(x1.w, w3.x, a1[0]); a1[1] = fmaf(x1.w, w3.y, a1[1]);
                    a1[2] = fmaf(x1.w, w3.z, a1[2]); a1[3] = fmaf(x1.w, w3.w, a1[3]);

                    a2[0] = fmaf(x2.x, w0.x, a2[0]); a2[1] = fmaf(x2.x, w0.y, a2[1]);
                    a2[2] = fmaf(x2.x, w0.z, a2[2]); a2[3] = fmaf(x2.x, w0.w, a2[3]);
                    a2[0] = fmaf(x2.y, w1.x, a2[0]); a2[1] = fmaf(x2.y, w1.y, a2[1]);
                    a2[2] = fmaf(x2.y, w1.z, a2[2]); a2[3] = fmaf(x2.y, w1.w, a2[3]);
                    a2[0] = fmaf(x2.z, w2.x, a2[0]); a2[1] = fmaf(x2.z, w2.y, a2[1]);
                    a2[2] = fmaf(x2.z, w2.z, a2[2]); a2[3] = fmaf(x2.z, w2.w, a2[3]);
                    a2[0] = fmaf(x2.w, w3.x, a2[0]); a2[1] = fmaf(x2.w, w3.y, a2[1]);
                    a2[2] = fmaf(x2.w, w3.z, a2[2]); a2[3] = fmaf(x2.w, w3.w, a2[3]);

                    a3[0] = fmaf(x3.x, w0.x, a3[0]); a3[1] = fmaf(x3.x, w0.y, a3[1]);
                    a3[2] = fmaf(x3.x, w0.z, a3[2]); a3[3] = fmaf(x3.x, w0.w, a3[3]);
                    a3[0] = fmaf(x3.y, w1.x, a3[0]); a3[1] = fmaf(x3.y, w1.y, a3[1]);
                    a3[2] = fmaf(x3.y, w1.z, a3[2]); a3[3] = fmaf(x3.y, w1.w, a3[3]);
                    a3[0] = fmaf(x3.z, w2.x, a3[0]); a3[1] = fmaf(x3.z, w2.y, a3[1]);
                    a3[2] = fmaf(x3.z, w2.z, a3[2]); a3[3] = fmaf(x3.z, w2.w, a3[3]);
                    a3[0] = fmaf(x3.w, w3.x, a3[0]); a3[1] = fmaf(x3.w, w3.y, a3[1]);
                    a3[2] = fmaf(x3.w, w3.z, a3[2]); a3[3] = fmaf(x3.w, w3.w, a3[3]);
                }
                const int rrow = rl + rsub;
                float* o0 = sp + (size_t)((bb + 0) * RSTAGE + rrow) * SPS + c4 * 4;
                float* o1 = sp + (size_t)((bb + 1) * RSTAGE + rrow) * SPS + c4 * 4;
                float* o2 = sp + (size_t)((bb + 2) * RSTAGE + rrow) * SPS + c4 * 4;
                float* o3 = sp + (size_t)((bb + 3) * RSTAGE + rrow) * SPS + c4 * 4;
#pragma unroll
                for (int q = 0; q < 4; q++) { o0[q] = a0[q]; o1[q] = a1[q]; o2[q] = a2[q]; o3[q] = a3[q]; }
            }
        }
        __syncthreads();
        if (stage == 0) {
            // pull stage-A register rows: warp (b = wid&7, rh = wid>>3); lane rows rh*64+lane, +32
            const int bloc = wid & 7, rh = wid >> 3;
            const float* rA = sp + (size_t)(bloc * RSTAGE + rh * 64 + lane) * SPS;
            const float* rB = sp + (size_t)(bloc * RSTAGE + rh * 64 + 32 + lane) * SPS;
#pragma unroll
            for (int o = 0; o < 32; o++) { rf[o] = rA[o]; rf[32 + o] = rB[o]; }
            __syncthreads();
        }
    }
    // SMEM now holds stage-B rows (routes 128..255 local)

    // ================= Phase 2: distributed routing =================
    const int bloc = wid & 7, rh = wid >> 3;
    const float* smA = sp + (size_t)(bloc * RSTAGE + rh * 64 + lane) * SPS;
    const float* smB = sp + (size_t)(bloc * RSTAGE + rh * 64 + 32 + lane) * SPS;
    float* Vb = Vsh + bloc * 32;

    for (int it = 0; it < NITERS; it++) {
        float w1, w2, w3, w4, m_cb = 0.f;
        if (it > 0) {
            float l1 = 0.f, l2 = 0.f, l3 = 0.f, l4 = 0.f;
#pragma unroll
            for (int o = 0; o < 32; o++) {
                float v = Vb[o];
                l1 = fmaf(rf[o], v, l1);
                l2 = fmaf(rf[32 + o], v, l2);
                l3 = fmaf(smA[o], v, l3);
                l4 = fmaf(smB[o], v, l4);
            }
            float m = fmaxf(fmaxf(l1, l2), fmaxf(l3, l4));
#pragma unroll
            for (int s = 16; s; s >>= 1) m = fmaxf(m, __shfl_xor_sync(0xffffffffu, m, s));
            if (lane == 0) wredM[wid] = m;
            __syncthreads();
            m_cb = fmaxf(wredM[bloc], wredM[bloc + 8]);
            w1 = __expf(l1 - m_cb); w2 = __expf(l2 - m_cb);
            w3 = __expf(l3 - m_cb); w4 = __expf(l4 - m_cb);
        } else {
            __syncthreads();                 // keep sync count uniform
            w1 = w2 = w3 = w4 = 1.f;         // uniform pass: m=0, Z counts routes
        }

        float Zl = w1 + w2 + w3 + w4;
#pragma unroll
        for (int s = 16; s; s >>= 1) Zl += __shfl_xor_sync(0xffffffffu, Zl, s);
        if (lane == 0) wredZ[wid] = Zl;

        float ps[32];
#pragma unroll
        for (int o = 0; o < 32; o++)
            ps[o] = w1 * rf[o] + w2 * rf[32 + o] + w3 * smA[o] + w4 * smB[o];
#pragma unroll
        for (int s = 16; s; s >>= 1) {
#pragma unroll
            for (int o = 0; o < 32; o++)
                ps[o] += __shfl_xor_sync(0xffffffffu, ps[o], s);
        }
        if (lane == 0) {
#pragma unroll
            for (int o = 0; o < 32; o++) wvec[wid * 32 + o] = ps[o];
        }
        __syncthreads();

        // CTA-level partials -> exch[bloc] = (m, Z, s~[32])
        if (rh == 0) {
            if (lane == 0) {
                exch[bloc * 34 + 0] = m_cb;
                exch[bloc * 34 + 1] = wredZ[bloc] + wredZ[bloc + 8];
            }
            exch[bloc * 34 + 2 + lane] = wvec[bloc * 32 + lane] + wvec[(bloc + 8) * 32 + lane];
        }
        __syncthreads();
        CLUSTER_SYNC();

        // Global combine (every warp, for its batch; identical on all CTAs)
        float mk = -3.402823e38f, Zk = 0.f;
        if (lane < CSZ) {
            mk = dsmem_ld(exch + bloc * 34 + 0, (uint32_t)lane);
            Zk = dsmem_ld(exch + bloc * 34 + 1, (uint32_t)lane);
        }
        float M = -3.402823e38f;
#pragma unroll
        for (int k = 0; k < CSZ; k++) M = fmaxf(M, __shfl_sync(0xffffffffu, mk, k));
        float Zg = 0.f;
#pragma unroll
        for (int k = 0; k < CSZ; k++)
            Zg += __shfl_sync(0xffffffffu, Zk, k) * __expf(__shfl_sync(0xffffffffu, mk, k) - M);

        float sv = 0.f;
#pragma unroll
        for (int k = 0; k < CSZ; k++)
            sv += dsmem_ld(exch + bloc * 34 + 2 + lane, (uint32_t)k) *
                  __expf(__shfl_sync(0xffffffffu, mk, k) - M);
        sv /= Zg;

        float nr = sv * sv;
#pragma unroll
        for (int s = 16; s; s >>= 1) nr += __shfl_xor_sync(0xffffffffu, nr, s);
        float scale = (nr / (1.0f + nr)) * rsqrtf(nr);
        float v = scale * sv;

        if (rh == 0) Vb[lane] += v;
        if (it == NITERS - 1 && rank == (uint32_t)bloc && rh == 0)
            out[((size_t)(b0g + bloc) * NCAPS + c) * OUTDIM + lane] = v;

        __syncthreads();
        CLUSTER_SYNC();   // exch reusable next iter; also keeps CTAs alive for DSMEM
    }
}

extern "C" void kernel_launch(void* const* d_in, const int* in_sizes, int n_in,
                              void* d_out, int out_size)
{
    const float* x = (const float*)d_in[0];         // [64, 2048, 16]
    const float* W = (const float*)d_in[1];         // [32, 2048, 16, 32]
    float* out = (float*)d_out;                     // [64, 32, 32]

    cudaFuncSetAttribute(caps_cluster_kernel,
                         cudaFuncAttributeMaxDynamicSharedMemorySize, SMEM_BYTES);

    cudaLaunchConfig_t cfg = {};
    cfg.gridDim = dim3(NCAPS * (BATCH / BPC) * CSZ);   // 2048 CTAs = 256 clusters of 8
    cfg.blockDim = dim3(THREADS);
    cfg.dynamicSmemBytes = SMEM_BYTES;
    cudaLaunchAttribute attrs[1];
    attrs[0].id = cudaLaunchAttributeClusterDimension;
    attrs[0].val.clusterDim.x = CSZ;
    attrs[0].val.clusterDim.y = 1;
    attrs[0].val.clusterDim.z = 1;
    cfg.attrs = attrs;
    cfg.numAttrs = 1;
    cudaLaunchKernelEx(&cfg, caps_cluster_kernel, x, W, out);
}

// round 8
// speedup vs baseline: 1.3345x; 1.3345x over previous
#include <cuda_runtime.h>
#include <cuda_fp16.h>
#include <cstddef>
#include <cstdint>

#define BATCH   64
#define NCAPS   32
#define NROUTES 2048
#define INDIM   16
#define OUTDIM  32
#define NITERS  3
#define THREADS 512
#define NWARPS  16

// Prior rows stored as half2[16] with stride 17 (half2 units) -> conflict-free
#define SPH 17

// ---- SMEM layout ----
#define SP_HALF2S   (1024 * SPH)
#define OFF_SP0     0
#define OFF_SP1     SP_HALF2S
#define OFF_SCRATCH (2 * SP_HALF2S)
#define N_SCRATCH   (32 + 32 + 16 + NWARPS * 32 + 4)
#define SMEM_BYTES  ((OFF_SCRATCH + N_SCRATCH) * 4)

// Quad-route warp scheme: lane l -> route (r4 + l/8), cols 4*(l%8)..+3.
// One pass over W feeds BOTH batches. x is front-loaded (8 LDG.128 issued
// before any W load) for deep MLP; W loads then stream per-g.
__device__ __forceinline__ void quad2(const float* __restrict__ x,
                                      const float* __restrict__ W,
                                      int b0, int b1, int c, int r4,
                                      int rsub, int c4,
                                      float aX[4], float aY[4])
{
    const int r = r4 + rsub;
    const float4* xr0 = reinterpret_cast<const float4*>(x + ((size_t)b0 * NROUTES + r) * INDIM);
    const float4* xr1 = reinterpret_cast<const float4*>(x + ((size_t)b1 * NROUTES + r) * INDIM);
    const float4* wr  = reinterpret_cast<const float4*>(
        W + ((size_t)c * NROUTES + r) * (INDIM * OUTDIM)) + c4;   // stride per i: 8 float4

    // Front-load all x (8 independent loads in flight immediately)
    float4 xa0 = __ldg(xr0 + 0), xa1 = __ldg(xr0 + 1), xa2 = __ldg(xr0 + 2), xa3 = __ldg(xr0 + 3);
    float4 xb0 = __ldg(xr1 + 0), xb1 = __ldg(xr1 + 1), xb2 = __ldg(xr1 + 2), xb3 = __ldg(xr1 + 3);

    aX[0] = aX[1] = aX[2] = aX[3] = 0.f;
    aY[0] = aY[1] = aY[2] = aY[3] = 0.f;

#pragma unroll
    for (int g = 0; g < 4; g++) {
        float4 xa = (g == 0) ? xa0 : (g == 1) ? xa1 : (g == 2) ? xa2 : xa3;
        float4 xb = (g == 0) ? xb0 : (g == 1) ? xb1 : (g == 2) ? xb2 : xb3;
        float4 w0 = __ldg(wr + (g * 4 + 0) * 8);
        float4 w1 = __ldg(wr + (g * 4 + 1) * 8);
        float4 w2 = __ldg(wr + (g * 4 + 2) * 8);
        float4 w3 = __ldg(wr + (g * 4 + 3) * 8);

        aX[0] = fmaf(xa.x, w0.x, aX[0]); aX[1] = fmaf(xa.x, w0.y, aX[1]);
        aX[2] = fmaf(xa.x, w0.z, aX[2]); aX[3] = fmaf(xa.x, w0.w, aX[3]);
        aX[0] = fmaf(xa.y, w1.x, aX[0]); aX[1] = fmaf(xa.y, w1.y, aX[1]);
        aX[2] = fmaf(xa.y, w1.z, aX[2]); aX[3] = fmaf(xa.y, w1.w, aX[3]);
        aX[0] = fmaf(xa.z, w2.x, aX[0]); aX[1] = fmaf(xa.z, w2.y, aX[1]);
        aX[2] = fmaf(xa.z, w2.z, aX[2]); aX[3] = fmaf(xa.z, w2.w, aX[3]);
        aX[0] = fmaf(xa.w, w3.x, aX[0]); aX[1] = fmaf(xa.w, w3.y, aX[1]);
        aX[2] = fmaf(xa.w, w3.z, aX[2]); aX[3] = fmaf(xa.w, w3.w, aX[3]);

        aY[0] = fmaf(xb.x, w0.x, aY[0]); aY[1] = fmaf(xb.x, w0.y, aY[1]);
        aY[2] = fmaf(xb.x, w0.z, aY[2]); aY[3] = fmaf(xb.x, w0.w, aY[3]);
        aY[0] = fmaf(xb.y, w1.x, aY[0]); aY[1] = fmaf(xb.y, w1.y, aY[1]);
        aY[2] = fmaf(xb.y, w1.z, aY[2]); aY[3] = fmaf(xb.y, w1.w, aY[3]);
        aY[0] = fmaf(xb.z, w2.x, aY[0]); aY[1] = fmaf(xb.z, w2.y, aY[1]);
        aY[2] = fmaf(xb.z, w2.z, aY[2]); aY[3] = fmaf(xb.z, w2.w, aY[3]);
        aY[0] = fmaf(xb.w, w3.x, aY[0]); aY[1] = fmaf(xb.w, w3.y, aY[1]);
        aY[2] = fmaf(xb.w, w3.z, aY[2]); aY[3] = fmaf(xb.w, w3.w, aY[3]);
    }
}

__global__ void __launch_bounds__(THREADS, 1)
caps_route_kernel(const float* __restrict__ x,
                  const float* __restrict__ W,
                  float* __restrict__ out)
{
    extern __shared__ __half2 smh[];
    __half2* sp0 = smh + OFF_SP0;
    __half2* sp1 = smh + OFF_SP1;
    float* scr  = reinterpret_cast<float*>(smh + OFF_SCRATCH);
    float* Vsh  = scr;            // 32
    float* sred = scr + 32;       // 32
    float* wred = scr + 64;       // 16
    float* wvec = scr + 80;       // 16*32
    float* scal = scr + 80 + NWARPS * 32;  // 4

    const int t    = threadIdx.x;
    const int lane = t & 31;
    const int wid  = t >> 5;
    const int rsub = lane >> 3;
    const int c4   = lane & 7;
    const int bp   = blockIdx.x & (NCAPS - 1);   // 0..31
    const int c    = blockIdx.x >> 5;
    const int b0   = 2 * bp, b1 = 2 * bp + 1;

    // ---------------- Phase 1a: routes 0..1023 ----------------
    {
        const int base = wid * 64;
#pragma unroll 2
        for (int j = 0; j < 64; j += 4) {
            float aX[4], aY[4];
            quad2(x, W, b0, b1, c, base + j, rsub, c4, aX, aY);
            const int row = base + j + rsub;
            __half2* r0 = sp0 + (size_t)row * SPH + c4 * 2;
            __half2* r1 = sp1 + (size_t)row * SPH + c4 * 2;
            r0[0] = __floats2half2_rn(aX[0], aX[1]);
            r0[1] = __floats2half2_rn(aX[2], aX[3]);
            r1[0] = __floats2half2_rn(aY[0], aY[1]);
            r1[1] = __floats2half2_rn(aY[2], aY[3]);
        }
    }
    __syncthreads();

    // Pull register copies: batch0 routes t, t+512 ; batch1 routes t, t+512
    __half2 A0[16], B0[16], A1[16], B1[16];
    {
        const __half2* pA0 = sp0 + (size_t)t * SPH;
        const __half2* pB0 = sp0 + (size_t)(512 + t) * SPH;
        const __half2* pA1 = sp1 + (size_t)t * SPH;
        const __half2* pB1 = sp1 + (size_t)(512 + t) * SPH;
#pragma unroll
        for (int j = 0; j < 16; j++) {
            A0[j] = pA0[j]; B0[j] = pB0[j];
            A1[j] = pA1[j]; B1[j] = pB1[j];
        }
    }
    __syncthreads();

    // ---------------- Phase 1b: routes 1024..2047 overwrite ----------------
    {
        const int base = wid * 64;
#pragma unroll 2
        for (int j = 0; j < 64; j += 4) {
            float aX[4], aY[4];
            quad2(x, W, b0, b1, c, 1024 + base + j, rsub, c4, aX, aY);
            const int row = base + j + rsub;
            __half2* r0 = sp0 + (size_t)row * SPH + c4 * 2;
            __half2* r1 = sp1 + (size_t)row * SPH + c4 * 2;
            r0[0] = __floats2half2_rn(aX[0], aX[1]);
            r0[1] = __floats2half2_rn(aX[2], aX[3]);
            r1[0] = __floats2half2_rn(aY[0], aY[1]);
            r1[1] = __floats2half2_rn(aY[2], aY[3]);
        }
    }
    __syncthreads();

    // ---------------- Phase 2: routing, batch-sequential ----------------
    for (int bb = 0; bb < 2; bb++) {
        const __half2* A   = bb ? A1 : A0;
        const __half2* B   = bb ? B1 : B0;
        const __half2* spC = (bb ? sp1 : sp0) + (size_t)t * SPH;          // route 1024+t
        const __half2* spD = (bb ? sp1 : sp0) + (size_t)(512 + t) * SPH;  // route 1536+t
        const int bout = bb ? b1 : b0;

        if (t < 32) Vsh[t] = 0.f;
        __syncthreads();

        for (int it = 0; it < NITERS; it++) {
            float p0, p1, p2, p3;
            if (it == 0) {
                p0 = p1 = p2 = p3 = 1.0f / (float)NROUTES;
            } else {
                float l0 = 0.f, l1 = 0.f, l2 = 0.f, l3 = 0.f;
#pragma unroll
                for (int j = 0; j < 16; j++) {
                    float v0 = Vsh[2 * j], v1 = Vsh[2 * j + 1];
                    float2 a = __half22float2(A[j]);
                    float2 b2 = __half22float2(B[j]);
                    float2 cc = __half22float2(spC[j]);
                    float2 dd = __half22float2(spD[j]);
                    l0 += a.x * v0 + a.y * v1;
                    l1 += b2.x * v0 + b2.y * v1;
                    l2 += cc.x * v0 + cc.y * v1;
                    l3 += dd.x * v0 + dd.y * v1;
                }
                float m = fmaxf(fmaxf(l0, l1), fmaxf(l2, l3));
#pragma unroll
                for (int s = 16; s; s >>= 1) m = fmaxf(m, __shfl_xor_sync(0xffffffffu, m, s));
                if (lane == 0) wred[wid] = m;
                __syncthreads();
                if (wid == 0) {
                    float mm = (lane < NWARPS) ? wred[lane] : -3.402823e38f;
#pragma unroll
                    for (int s = 16; s; s >>= 1) mm = fmaxf(mm, __shfl_xor_sync(0xffffffffu, mm, s));
                    if (lane == 0) scal[0] = mm;
                }
                __syncthreads();
                const float bmax = scal[0];

                float e0 = __expf(l0 - bmax);
                float e1 = __expf(l1 - bmax);
                float e2 = __expf(l2 - bmax);
                float e3 = __expf(l3 - bmax);
                float zs = e0 + e1 + e2 + e3;
#pragma unroll
                for (int s = 16; s; s >>= 1) zs += __shfl_xor_sync(0xffffffffu, zs, s);
                if (lane == 0) wred[wid] = zs;
                __syncthreads();
                if (wid == 0) {
                    float zz = (lane < NWARPS) ? wred[lane] : 0.f;
#pragma unroll
                    for (int s = 16; s; s >>= 1) zz += __shfl_xor_sync(0xffffffffu, zz, s);
                    if (lane == 0) scal[1] = zz;
                }
                __syncthreads();
                const float invZ = 1.0f / scal[1];
                p0 = e0 * invZ; p1 = e1 * invZ; p2 = e2 * invZ; p3 = e3 * invZ;
            }

            // s = sum_n probs_n * p_n  (deterministic tree)
            float ps[OUTDIM];
#pragma unroll
            for (int j = 0; j < 16; j++) {
                float2 a = __half22float2(A[j]);
                float2 b2 = __half22float2(B[j]);
                float2 cc = __half22float2(spC[j]);
                float2 dd = __half22float2(spD[j]);
                ps[2 * j]     = p0 * a.x + p1 * b2.x + p2 * cc.x + p3 * dd.x;
                ps[2 * j + 1] = p0 * a.y + p1 * b2.y + p2 * cc.y + p3 * dd.y;
            }
#pragma unroll
            for (int s = 16; s; s >>= 1) {
#pragma unroll
                for (int o = 0; o < OUTDIM; o++)
                    ps[o] += __shfl_xor_sync(0xffffffffu, ps[o], s);
            }
            if (lane == 0) {
#pragma unroll
                for (int o = 0; o < OUTDIM; o++) wvec[wid * 32 + o] = ps[o];
            }
            __syncthreads();
            if (t < 32) {
                float sv = 0.f;
#pragma unroll
                for (int w = 0; w < NWARPS; w++) sv += wvec[w * 32 + t];
                sred[t] = sv;
            }
            __syncthreads();

            if (t < 32) {
                float nr = 0.f;
#pragma unroll
                for (int o = 0; o < OUTDIM; o++) { float sv = sred[o]; nr += sv * sv; }
                float scale = (nr / (1.0f + nr)) * rsqrtf(nr);
                float v = scale * sred[t];
                Vsh[t] += v;
                if (it == NITERS - 1)
                    out[((size_t)bout * NCAPS + c) * OUTDIM + t] = v;
            }
            __syncthreads();
        }
    }
}

extern "C" void kernel_launch(void* const* d_in, const int* in_sizes, int n_in,
                              void* d_out, int out_size)
{
    const float* x = (const float*)d_in[0];         // [64, 2048, 16]
    const float* W = (const float*)d_in[1];         // [32, 2048, 16, 32]
    float* out = (float*)d_out;                     // [64, 32, 32]

    cudaFuncSetAttribute(caps_route_kernel,
                         cudaFuncAttributeMaxDynamicSharedMemorySize, SMEM_BYTES);

    dim3 grid(NCAPS * (BATCH / 2));   // bid = c*32 + bp ; each CTA does batches 2bp, 2bp+1
    caps_route_kernel<<<grid, THREADS, SMEM_BYTES>>>(x, W, out);
}